// round 1
// baseline (speedup 1.0000x reference)
#include <cuda_runtime.h>
#include <math.h>

#define NNODES 100000
#define NEDGES 1000000
#define FDIM   128
#define F2DIM  188
#define NCLS   47
#define NHEAD  4
#define BN_EPS 1e-5f

// ---------------- scratch (device globals; no allocation allowed) ----------------
__device__ float g_fs[(size_t)NNODES * F2DIM];
__device__ float g_fd[(size_t)NNODES * F2DIM];
__device__ float g_res[(size_t)NNODES * F2DIM];
__device__ float g_hA[(size_t)NNODES * FDIM];
__device__ float g_hB[(size_t)NNODES * FDIM];
__device__ int   g_rowptr[NNODES + 1];
__device__ float g_bnsum[FDIM];
__device__ float g_bnsq[FDIM];

// ---------------- CSR row_ptr from sorted dst ----------------
__global__ void build_rowptr(const int* __restrict__ dst, int E, int N) {
    int e = blockIdx.x * blockDim.x + threadIdx.x;
    if (e >= E) return;
    int d = dst[e];
    int dprev = (e == 0) ? -1 : dst[e - 1];
    for (int n = dprev + 1; n <= d; n++) g_rowptr[n] = e;
    if (e == E - 1) {
        for (int n = d + 1; n <= N; n++) g_rowptr[n] = E;
    }
}

// ---------------- fp32 tiled GEMM: C[nrows,ncols] = A[nrows,K] @ W[K,ncols] + bias ----------------
// 64x64 tile, BK=16, 256 threads, 4x4 per-thread register tile.
__global__ void gemm_bias(const float* __restrict__ A, const float* __restrict__ W,
                          const float* __restrict__ bias, float* __restrict__ C,
                          int nrows, int K, int ncols) {
    __shared__ float As[16][64];
    __shared__ float Ws[16][64];
    int tid = threadIdx.x;
    int tx = tid & 15, ty = tid >> 4;
    int row0 = blockIdx.x * 64;
    int col0 = blockIdx.y * 64;
    float acc[4][4];
#pragma unroll
    for (int i = 0; i < 4; i++)
#pragma unroll
        for (int j = 0; j < 4; j++) acc[i][j] = 0.f;

    for (int k0 = 0; k0 < K; k0 += 16) {
        {   // A tile: 64 rows x 16 k, 4 elems/thread (coalesced over k)
            int r  = tid >> 2;
            int kb = (tid & 3) * 4;
#pragma unroll
            for (int j = 0; j < 4; j++) {
                int kk = kb + j;
                int gr = row0 + r, gk = k0 + kk;
                As[kk][r] = (gr < nrows && gk < K) ? A[(size_t)gr * K + gk] : 0.f;
            }
        }
        {   // W tile: 16 k x 64 cols, coalesced over cols
            int kk = tid >> 4;
            int cb = (tid & 15) * 4;
#pragma unroll
            for (int j = 0; j < 4; j++) {
                int c  = cb + j;
                int gc = col0 + c, gk = k0 + kk;
                Ws[kk][c] = (gc < ncols && gk < K) ? W[(size_t)gk * ncols + gc] : 0.f;
            }
        }
        __syncthreads();
#pragma unroll
        for (int kk = 0; kk < 16; kk++) {
            float a[4], w[4];
#pragma unroll
            for (int i = 0; i < 4; i++) a[i] = As[kk][ty * 4 + i];
#pragma unroll
            for (int j = 0; j < 4; j++) w[j] = Ws[kk][tx * 4 + j];
#pragma unroll
            for (int i = 0; i < 4; i++)
#pragma unroll
                for (int j = 0; j < 4; j++) acc[i][j] = fmaf(a[i], w[j], acc[i][j]);
        }
        __syncthreads();
    }
#pragma unroll
    for (int i = 0; i < 4; i++) {
        int gr = row0 + ty * 4 + i;
        if (gr >= nrows) continue;
#pragma unroll
        for (int j = 0; j < 4; j++) {
            int gc = col0 + tx * 4 + j;
            if (gc < ncols) C[(size_t)gr * ncols + gc] = acc[i][j] + bias[gc];
        }
    }
}

// ---------------- GATv2 aggregation, F=128 (H=4, D=32); warp per node; online softmax ----------------
// out = relu(softmax-aggregate + res)   (relu fused: both layer0/1 outputs feed relu)
__global__ void gat_agg128(const float* __restrict__ fs, const float* __restrict__ fd,
                           const float* __restrict__ attn, const float* __restrict__ res,
                           float* __restrict__ out, const int* __restrict__ srcidx, int N) {
    int warp = (blockIdx.x * blockDim.x + threadIdx.x) >> 5;
    int lane = threadIdx.x & 31;
    if (warp >= N) return;
    int n = warp;
    float fdv[4], av[4], acc[4], mh[4], sh[4];
#pragma unroll
    for (int h = 0; h < 4; h++) {
        fdv[h] = fd[(size_t)n * 128 + h * 32 + lane];
        av[h]  = attn[h * 32 + lane];
        acc[h] = 0.f; mh[h] = -1e30f; sh[h] = 0.f;
    }
    int e0 = g_rowptr[n], e1 = g_rowptr[n + 1];
    for (int e = e0; e < e1; e++) {
        int si = __ldg(&srcidx[e]);
        const float* fsp = fs + (size_t)si * 128;
        float fsv[4];
#pragma unroll
        for (int h = 0; h < 4; h++) fsv[h] = __ldg(&fsp[h * 32 + lane]);
#pragma unroll
        for (int h = 0; h < 4; h++) {
            float v = fsv[h] + fdv[h];
            v = (v > 0.f) ? v : 0.2f * v;
            float t = v * av[h];
            t += __shfl_xor_sync(0xffffffffu, t, 16);
            t += __shfl_xor_sync(0xffffffffu, t, 8);
            t += __shfl_xor_sync(0xffffffffu, t, 4);
            t += __shfl_xor_sync(0xffffffffu, t, 2);
            t += __shfl_xor_sync(0xffffffffu, t, 1);
            if (t > mh[h]) {
                float c = __expf(mh[h] - t);
                acc[h] *= c; sh[h] *= c; mh[h] = t;
            }
            float p = __expf(t - mh[h]);
            sh[h] += p;
            acc[h] = fmaf(p, fsv[h], acc[h]);
        }
    }
    bool has = (e1 > e0);
#pragma unroll
    for (int h = 0; h < 4; h++) {
        float v = has ? (acc[h] / sh[h]) : 0.f;
        v += res[(size_t)n * 128 + h * 32 + lane];
        out[(size_t)n * 128 + h * 32 + lane] = fmaxf(v, 0.f);
    }
}

// ---------------- Layer-2 aggregation (C=47) fused with head-mean + log_softmax ----------------
__global__ void gat_agg_final(const float* __restrict__ fs, const float* __restrict__ fd,
                              const float* __restrict__ attn, const float* __restrict__ res,
                              float* __restrict__ out, const int* __restrict__ srcidx, int N) {
    int warp = (blockIdx.x * blockDim.x + threadIdx.x) >> 5;
    int lane = threadIdx.x & 31;
    if (warp >= N) return;
    int n = warp;
    bool has2 = (lane < 15);  // second class slot: c = 32 + lane < 47
    float fdv[4][2], av[4][2], acc[4][2], mh[4], sh[4];
#pragma unroll
    for (int h = 0; h < 4; h++) {
        fdv[h][0] = fd[(size_t)n * 188 + h * 47 + lane];
        av[h][0]  = attn[h * 47 + lane];
        fdv[h][1] = has2 ? fd[(size_t)n * 188 + h * 47 + 32 + lane] : 0.f;
        av[h][1]  = has2 ? attn[h * 47 + 32 + lane] : 0.f;
        acc[h][0] = 0.f; acc[h][1] = 0.f; mh[h] = -1e30f; sh[h] = 0.f;
    }
    int e0 = g_rowptr[n], e1 = g_rowptr[n + 1];
    for (int e = e0; e < e1; e++) {
        int si = __ldg(&srcidx[e]);
        const float* fsp = fs + (size_t)si * 188;
        float fsv[4][2];
#pragma unroll
        for (int h = 0; h < 4; h++) {
            fsv[h][0] = __ldg(&fsp[h * 47 + lane]);
            fsv[h][1] = has2 ? __ldg(&fsp[h * 47 + 32 + lane]) : 0.f;
        }
#pragma unroll
        for (int h = 0; h < 4; h++) {
            float v0 = fsv[h][0] + fdv[h][0];
            v0 = (v0 > 0.f) ? v0 : 0.2f * v0;
            float v1 = fsv[h][1] + fdv[h][1];
            v1 = (v1 > 0.f) ? v1 : 0.2f * v1;
            float t = v0 * av[h][0] + v1 * av[h][1];
            t += __shfl_xor_sync(0xffffffffu, t, 16);
            t += __shfl_xor_sync(0xffffffffu, t, 8);
            t += __shfl_xor_sync(0xffffffffu, t, 4);
            t += __shfl_xor_sync(0xffffffffu, t, 2);
            t += __shfl_xor_sync(0xffffffffu, t, 1);
            if (t > mh[h]) {
                float c = __expf(mh[h] - t);
                acc[h][0] *= c; acc[h][1] *= c; sh[h] *= c; mh[h] = t;
            }
            float p = __expf(t - mh[h]);
            sh[h] += p;
            acc[h][0] = fmaf(p, fsv[h][0], acc[h][0]);
            acc[h][1] = fmaf(p, fsv[h][1], acc[h][1]);
        }
    }
    bool has = (e1 > e0);
    float outv[2];
#pragma unroll
    for (int j = 0; j < 2; j++) {
        float sm = 0.f;
#pragma unroll
        for (int h = 0; h < 4; h++) {
            float v = has ? (acc[h][j] / sh[h]) : 0.f;
            if (j == 0)       v += res[(size_t)n * 188 + h * 47 + lane];
            else if (has2)    v += res[(size_t)n * 188 + h * 47 + 32 + lane];
            sm += v;
        }
        outv[j] = sm * 0.25f;
    }
    // log_softmax over 47 classes held as (lane -> c=lane, c=32+lane if lane<15)
    float lm = outv[0];
    if (has2) lm = fmaxf(lm, outv[1]);
    lm = fmaxf(lm, __shfl_xor_sync(0xffffffffu, lm, 16));
    lm = fmaxf(lm, __shfl_xor_sync(0xffffffffu, lm, 8));
    lm = fmaxf(lm, __shfl_xor_sync(0xffffffffu, lm, 4));
    lm = fmaxf(lm, __shfl_xor_sync(0xffffffffu, lm, 2));
    lm = fmaxf(lm, __shfl_xor_sync(0xffffffffu, lm, 1));
    float ls = __expf(outv[0] - lm) + (has2 ? __expf(outv[1] - lm) : 0.f);
    ls += __shfl_xor_sync(0xffffffffu, ls, 16);
    ls += __shfl_xor_sync(0xffffffffu, ls, 8);
    ls += __shfl_xor_sync(0xffffffffu, ls, 4);
    ls += __shfl_xor_sync(0xffffffffu, ls, 2);
    ls += __shfl_xor_sync(0xffffffffu, ls, 1);
    float lse = lm + logf(ls);
    out[(size_t)n * 47 + lane] = outv[0] - lse;
    if (has2) out[(size_t)n * 47 + 32 + lane] = outv[1] - lse;
}

// ---------------- BatchNorm (training batch stats), relu fused into apply ----------------
__global__ void bn_zero() {
    g_bnsum[threadIdx.x] = 0.f;
    g_bnsq[threadIdx.x]  = 0.f;
}

__global__ void bn_stats(const float* __restrict__ X, int nrows) {
    int col = threadIdx.x;  // 128 threads
    float s = 0.f, sq = 0.f;
    for (int r = blockIdx.x; r < nrows; r += gridDim.x) {
        float v = X[(size_t)r * 128 + col];
        s += v; sq += v * v;
    }
    atomicAdd(&g_bnsum[col], s);
    atomicAdd(&g_bnsq[col], sq);
}

__global__ void bn_apply(const float* __restrict__ X, float* __restrict__ Y,
                         const float* __restrict__ g, const float* __restrict__ b, int nrows) {
    int idx = blockIdx.x * blockDim.x + threadIdx.x;
    if (idx >= nrows * 128) return;
    int col = idx & 127;
    float inv_n = 1.0f / (float)nrows;
    float mu  = g_bnsum[col] * inv_n;
    float var = g_bnsq[col] * inv_n - mu * mu;
    float v = g[col] * (X[idx] - mu) * rsqrtf(var + BN_EPS) + b[col];
    Y[idx] = fmaxf(v, 0.f);
}

// ---------------- launch ----------------
extern "C" void kernel_launch(void* const* d_in, const int* in_sizes, int n_in,
                              void* d_out, int out_size) {
    const float* x     = (const float*)d_in[0];
    const int*   src   = (const int*)d_in[1];
    const int*   dst   = (const int*)d_in[2];
    const float* Wsrc0 = (const float*)d_in[3];  const float* bsrc0 = (const float*)d_in[4];
    const float* Wdst0 = (const float*)d_in[5];  const float* bdst0 = (const float*)d_in[6];
    const float* attn0 = (const float*)d_in[7];
    const float* Wres0 = (const float*)d_in[8];  const float* bres0 = (const float*)d_in[9];
    const float* Wsrc1 = (const float*)d_in[10]; const float* bsrc1 = (const float*)d_in[11];
    const float* Wdst1 = (const float*)d_in[12]; const float* bdst1 = (const float*)d_in[13];
    const float* attn1 = (const float*)d_in[14];
    const float* Wsrc2 = (const float*)d_in[15]; const float* bsrc2 = (const float*)d_in[16];
    const float* Wdst2 = (const float*)d_in[17]; const float* bdst2 = (const float*)d_in[18];
    const float* attn2 = (const float*)d_in[19];
    const float* Wres2 = (const float*)d_in[20]; const float* bres2 = (const float*)d_in[21];
    const float* g0    = (const float*)d_in[22]; const float* be0   = (const float*)d_in[23];
    const float* g1    = (const float*)d_in[24]; const float* be1   = (const float*)d_in[25];
    float* out = (float*)d_out;

    float *fs, *fd, *res, *hA, *hB;
    cudaGetSymbolAddress((void**)&fs,  g_fs);
    cudaGetSymbolAddress((void**)&fd,  g_fd);
    cudaGetSymbolAddress((void**)&res, g_res);
    cudaGetSymbolAddress((void**)&hA,  g_hA);
    cudaGetSymbolAddress((void**)&hB,  g_hB);

    const int N = NNODES, E = NEDGES;
    dim3 gB((N + 63) / 64, 2);
    dim3 gB2((N + 63) / 64, 3);
    int aggGrid = N / 8;                 // 8 warps/block, one node per warp
    int applyGrid = (N * 128 + 255) / 256;

    build_rowptr<<<(E + 255) / 256, 256>>>(dst, E, N);

    // ---- layer 0: x[N,100] -> 128, Linear residual ----
    gemm_bias<<<gB, 256>>>(x, Wsrc0, bsrc0, fs, N, 100, 128);
    gemm_bias<<<gB, 256>>>(x, Wdst0, bdst0, fd, N, 100, 128);
    gemm_bias<<<gB, 256>>>(x, Wres0, bres0, res, N, 100, 128);
    gat_agg128<<<aggGrid, 256>>>(fs, fd, attn0, res, hA, src, N);
    bn_zero<<<1, 128>>>();
    bn_stats<<<512, 128>>>(hA, N);
    bn_apply<<<applyGrid, 256>>>(hA, hB, g0, be0, N);

    // ---- layer 1: 128 -> 128, Identity residual ----
    gemm_bias<<<gB, 256>>>(hB, Wsrc1, bsrc1, fs, N, 128, 128);
    gemm_bias<<<gB, 256>>>(hB, Wdst1, bdst1, fd, N, 128, 128);
    gat_agg128<<<aggGrid, 256>>>(fs, fd, attn1, hB, hA, src, N);
    bn_zero<<<1, 128>>>();
    bn_stats<<<512, 128>>>(hA, N);
    bn_apply<<<applyGrid, 256>>>(hA, hB, g1, be1, N);

    // ---- layer 2: 128 -> 188 (H=4, C=47), Linear residual; mean heads + log_softmax ----
    gemm_bias<<<gB2, 256>>>(hB, Wsrc2, bsrc2, fs, N, 128, 188);
    gemm_bias<<<gB2, 256>>>(hB, Wdst2, bdst2, fd, N, 128, 188);
    gemm_bias<<<gB2, 256>>>(hB, Wres2, bres2, res, N, 128, 188);
    gat_agg_final<<<aggGrid, 256>>>(fs, fd, attn2, res, out, src, N);
}

// round 3
// speedup vs baseline: 1.2054x; 1.2054x over previous
#include <cuda_runtime.h>
#include <math.h>

#define NNODES 100000
#define NEDGES 1000000
#define FDIM   128
#define F2DIM  188
#define NCLS   47
#define NHEAD  4
#define BN_EPS 1e-5f

// ---------------- scratch (device globals; no allocation allowed) ----------------
__device__ float g_fs[(size_t)NNODES * F2DIM];
__device__ float g_fd[(size_t)NNODES * F2DIM];
__device__ float g_res[(size_t)NNODES * F2DIM];
__device__ float g_hA[(size_t)NNODES * FDIM];
__device__ float g_hB[(size_t)NNODES * FDIM];
__device__ int   g_rowptr[NNODES + 1];
__device__ float g_bnsum[FDIM];
__device__ float g_bnsq[FDIM];

// ---------------- CSR row_ptr from sorted dst ----------------
__global__ void build_rowptr(const int* __restrict__ dst, int E, int N) {
    int e = blockIdx.x * blockDim.x + threadIdx.x;
    if (e >= E) return;
    int d = dst[e];
    int dprev = (e == 0) ? -1 : dst[e - 1];
    for (int n = dprev + 1; n <= d; n++) g_rowptr[n] = e;
    if (e == E - 1) {
        for (int n = d + 1; n <= N; n++) g_rowptr[n] = E;
    }
}

// ---------------- split-tf32 tensor-core GEMM ----------------
// C[nrows,ncols] = A[nrows,K] @ W[K,ncols] + bias, fp32-accurate via
// C = Ah*Bh + Ah*Bl + Al*Bh (hi/lo tf32 split).
// Block tile 128x64, BK=16, 256 threads (8 warps, each warp 32x32).

#define BM 128
#define BNT 64
#define BKT 16
#define ASTR 136   // mod 32 == 8 -> conflict-free fragment loads
#define BSTR 72    // mod 32 == 8

__device__ __forceinline__ float tf32_rna(float x) {
    float r;
    asm("cvt.rna.tf32.f32 %0, %1;" : "=f"(r) : "f"(x));
    return r;
}

__device__ __forceinline__ void mma_tf32(float* d, const float* a, const float* b) {
    asm volatile(
        "mma.sync.aligned.m16n8k8.row.col.f32.tf32.tf32.f32 "
        "{%0,%1,%2,%3}, {%4,%5,%6,%7}, {%8,%9}, {%0,%1,%2,%3};"
        : "+f"(d[0]), "+f"(d[1]), "+f"(d[2]), "+f"(d[3])
        : "r"(__float_as_uint(a[0])), "r"(__float_as_uint(a[1])),
          "r"(__float_as_uint(a[2])), "r"(__float_as_uint(a[3])),
          "r"(__float_as_uint(b[0])), "r"(__float_as_uint(b[1])));
}

__global__ __launch_bounds__(256, 2)
void gemm_tf32(const float* __restrict__ A, const float* __restrict__ W,
               const float* __restrict__ bias, float* __restrict__ C,
               int nrows, int K, int ncols) {
    __shared__ float Ah[BKT][ASTR];
    __shared__ float Al[BKT][ASTR];
    __shared__ float Bh[BKT][BSTR];
    __shared__ float Bl[BKT][BSTR];

    int tid = threadIdx.x;
    int warp = tid >> 5, lane = tid & 31;
    int wm = warp & 3;          // 0..3 -> m offset 32*wm
    int wn = warp >> 2;         // 0..1 -> n offset 32*wn
    int g = lane >> 2, t4 = lane & 3;
    int row0 = blockIdx.x * BM;
    int col0 = blockIdx.y * BNT;

    // loader mapping
    int a_row = tid >> 1;              // 0..127
    int a_kp  = (tid & 1) * 8;         // 0 or 8
    int b_kr  = tid >> 4;              // 0..15
    int b_nc  = (tid & 15) * 4;        // 0..60

    float acc[2][4][4];
#pragma unroll
    for (int mt = 0; mt < 2; mt++)
#pragma unroll
        for (int nt = 0; nt < 4; nt++)
#pragma unroll
            for (int r = 0; r < 4; r++) acc[mt][nt][r] = 0.f;

    bool arow_ok = (row0 + a_row) < nrows;
    const float* Arow = A + (size_t)(row0 + a_row) * K;

    for (int k0 = 0; k0 < K; k0 += BKT) {
        // ---- load A tile (128x16): 2 float4 per thread ----
#pragma unroll
        for (int q = 0; q < 2; q++) {
            int kk = k0 + a_kp + 4 * q;
            float4 v = make_float4(0.f, 0.f, 0.f, 0.f);
            if (arow_ok) {
                if (kk + 3 < K) {
                    v = *reinterpret_cast<const float4*>(Arow + kk);
                } else {
                    float tmp[4] = {0.f, 0.f, 0.f, 0.f};
                    for (int j = 0; j < 4; j++)
                        if (kk + j < K) tmp[j] = Arow[kk + j];
                    v = make_float4(tmp[0], tmp[1], tmp[2], tmp[3]);
                }
            }
            float vv[4] = {v.x, v.y, v.z, v.w};
#pragma unroll
            for (int j = 0; j < 4; j++) {
                float hi = tf32_rna(vv[j]);
                float lo = tf32_rna(vv[j] - hi);
                Ah[a_kp + 4 * q + j][a_row] = hi;
                Al[a_kp + 4 * q + j][a_row] = lo;
            }
        }
        // ---- load W tile (16x64): 1 float4 per thread ----
        {
            int kk = k0 + b_kr;
            int cc = col0 + b_nc;
            float4 v = make_float4(0.f, 0.f, 0.f, 0.f);
            if (kk < K && cc < ncols)   // ncols and col tiles are multiples of 4
                v = *reinterpret_cast<const float4*>(W + (size_t)kk * ncols + cc);
            float vv[4] = {v.x, v.y, v.z, v.w};
            float hi4[4], lo4[4];
#pragma unroll
            for (int j = 0; j < 4; j++) {
                hi4[j] = tf32_rna(vv[j]);
                lo4[j] = tf32_rna(vv[j] - hi4[j]);
            }
            *reinterpret_cast<float4*>(&Bh[b_kr][b_nc]) = make_float4(hi4[0], hi4[1], hi4[2], hi4[3]);
            *reinterpret_cast<float4*>(&Bl[b_kr][b_nc]) = make_float4(lo4[0], lo4[1], lo4[2], lo4[3]);
        }
        __syncthreads();

        // ---- 2 k-steps of m16n8k8 ----
#pragma unroll
        for (int ks = 0; ks < 2; ks++) {
            int kb = ks * 8;
            float ah[2][4], al[2][4];
#pragma unroll
            for (int mt = 0; mt < 2; mt++) {
                int mr = wm * 32 + mt * 16 + g;
                ah[mt][0] = Ah[kb + t4][mr];
                ah[mt][1] = Ah[kb + t4][mr + 8];
                ah[mt][2] = Ah[kb + t4 + 4][mr];
                ah[mt][3] = Ah[kb + t4 + 4][mr + 8];
                al[mt][0] = Al[kb + t4][mr];
                al[mt][1] = Al[kb + t4][mr + 8];
                al[mt][2] = Al[kb + t4 + 4][mr];
                al[mt][3] = Al[kb + t4 + 4][mr + 8];
            }
            float bh[4][2], bl[4][2];
#pragma unroll
            for (int nt = 0; nt < 4; nt++) {
                int nc = wn * 32 + nt * 8 + g;
                bh[nt][0] = Bh[kb + t4][nc];
                bh[nt][1] = Bh[kb + t4 + 4][nc];
                bl[nt][0] = Bl[kb + t4][nc];
                bl[nt][1] = Bl[kb + t4 + 4][nc];
            }
#pragma unroll
            for (int mt = 0; mt < 2; mt++)
#pragma unroll
                for (int nt = 0; nt < 4; nt++) {
                    mma_tf32(acc[mt][nt], ah[mt], bh[nt]);
                    mma_tf32(acc[mt][nt], ah[mt], bl[nt]);
                    mma_tf32(acc[mt][nt], al[mt], bh[nt]);
                }
        }
        __syncthreads();
    }

    // ---- epilogue: bias add + store (float2 per fragment row) ----
#pragma unroll
    for (int mt = 0; mt < 2; mt++) {
#pragma unroll
        for (int nt = 0; nt < 4; nt++) {
            int row = row0 + wm * 32 + mt * 16 + g;
            int col = col0 + wn * 32 + nt * 8 + 2 * t4;
            if (col < ncols) {   // col even, ncols even -> col+1 also valid
                float b0 = bias[col], b1 = bias[col + 1];
                if (row < nrows) {
                    float2 v = make_float2(acc[mt][nt][0] + b0, acc[mt][nt][1] + b1);
                    *reinterpret_cast<float2*>(C + (size_t)row * ncols + col) = v;
                }
                if (row + 8 < nrows) {
                    float2 v = make_float2(acc[mt][nt][2] + b0, acc[mt][nt][3] + b1);
                    *reinterpret_cast<float2*>(C + (size_t)(row + 8) * ncols + col) = v;
                }
            }
        }
    }
}

// ---------------- GATv2 aggregation, F=128 (H=4, D=32); warp per node; online softmax ----------------
__global__ void gat_agg128(const float* __restrict__ fs, const float* __restrict__ fd,
                           const float* __restrict__ attn, const float* __restrict__ res,
                           float* __restrict__ out, const int* __restrict__ srcidx, int N) {
    int warp = (blockIdx.x * blockDim.x + threadIdx.x) >> 5;
    int lane = threadIdx.x & 31;
    if (warp >= N) return;
    int n = warp;
    float fdv[4], av[4], acc[4], mh[4], sh[4];
#pragma unroll
    for (int h = 0; h < 4; h++) {
        fdv[h] = fd[(size_t)n * 128 + h * 32 + lane];
        av[h]  = attn[h * 32 + lane];
        acc[h] = 0.f; mh[h] = -1e30f; sh[h] = 0.f;
    }
    int e0 = g_rowptr[n], e1 = g_rowptr[n + 1];
    for (int e = e0; e < e1; e++) {
        int si = __ldg(&srcidx[e]);
        const float* fsp = fs + (size_t)si * 128;
        float fsv[4];
#pragma unroll
        for (int h = 0; h < 4; h++) fsv[h] = __ldg(&fsp[h * 32 + lane]);
#pragma unroll
        for (int h = 0; h < 4; h++) {
            float v = fsv[h] + fdv[h];
            v = (v > 0.f) ? v : 0.2f * v;
            float t = v * av[h];
            t += __shfl_xor_sync(0xffffffffu, t, 16);
            t += __shfl_xor_sync(0xffffffffu, t, 8);
            t += __shfl_xor_sync(0xffffffffu, t, 4);
            t += __shfl_xor_sync(0xffffffffu, t, 2);
            t += __shfl_xor_sync(0xffffffffu, t, 1);
            if (t > mh[h]) {
                float c = __expf(mh[h] - t);
                acc[h] *= c; sh[h] *= c; mh[h] = t;
            }
            float p = __expf(t - mh[h]);
            sh[h] += p;
            acc[h] = fmaf(p, fsv[h], acc[h]);
        }
    }
    bool has = (e1 > e0);
#pragma unroll
    for (int h = 0; h < 4; h++) {
        float v = has ? (acc[h] / sh[h]) : 0.f;
        v += res[(size_t)n * 128 + h * 32 + lane];
        out[(size_t)n * 128 + h * 32 + lane] = fmaxf(v, 0.f);
    }
}

// ---------------- Layer-2 aggregation (C=47) fused with head-mean + log_softmax ----------------
__global__ void gat_agg_final(const float* __restrict__ fs, const float* __restrict__ fd,
                              const float* __restrict__ attn, const float* __restrict__ res,
                              float* __restrict__ out, const int* __restrict__ srcidx, int N) {
    int warp = (blockIdx.x * blockDim.x + threadIdx.x) >> 5;
    int lane = threadIdx.x & 31;
    if (warp >= N) return;
    int n = warp;
    bool has2 = (lane < 15);  // second class slot: c = 32 + lane < 47
    float fdv[4][2], av[4][2], acc[4][2], mh[4], sh[4];
#pragma unroll
    for (int h = 0; h < 4; h++) {
        fdv[h][0] = fd[(size_t)n * 188 + h * 47 + lane];
        av[h][0]  = attn[h * 47 + lane];
        fdv[h][1] = has2 ? fd[(size_t)n * 188 + h * 47 + 32 + lane] : 0.f;
        av[h][1]  = has2 ? attn[h * 47 + 32 + lane] : 0.f;
        acc[h][0] = 0.f; acc[h][1] = 0.f; mh[h] = -1e30f; sh[h] = 0.f;
    }
    int e0 = g_rowptr[n], e1 = g_rowptr[n + 1];
    for (int e = e0; e < e1; e++) {
        int si = __ldg(&srcidx[e]);
        const float* fsp = fs + (size_t)si * 188;
        float fsv[4][2];
#pragma unroll
        for (int h = 0; h < 4; h++) {
            fsv[h][0] = __ldg(&fsp[h * 47 + lane]);
            fsv[h][1] = has2 ? __ldg(&fsp[h * 47 + 32 + lane]) : 0.f;
        }
#pragma unroll
        for (int h = 0; h < 4; h++) {
            float v0 = fsv[h][0] + fdv[h][0];
            v0 = (v0 > 0.f) ? v0 : 0.2f * v0;
            float v1 = fsv[h][1] + fdv[h][1];
            v1 = (v1 > 0.f) ? v1 : 0.2f * v1;
            float t = v0 * av[h][0] + v1 * av[h][1];
            t += __shfl_xor_sync(0xffffffffu, t, 16);
            t += __shfl_xor_sync(0xffffffffu, t, 8);
            t += __shfl_xor_sync(0xffffffffu, t, 4);
            t += __shfl_xor_sync(0xffffffffu, t, 2);
            t += __shfl_xor_sync(0xffffffffu, t, 1);
            if (t > mh[h]) {
                float c = __expf(mh[h] - t);
                acc[h][0] *= c; acc[h][1] *= c; sh[h] *= c; mh[h] = t;
            }
            float p = __expf(t - mh[h]);
            sh[h] += p;
            acc[h][0] = fmaf(p, fsv[h][0], acc[h][0]);
            acc[h][1] = fmaf(p, fsv[h][1], acc[h][1]);
        }
    }
    bool has = (e1 > e0);
    float outv[2];
#pragma unroll
    for (int j = 0; j < 2; j++) {
        float sm = 0.f;
#pragma unroll
        for (int h = 0; h < 4; h++) {
            float v = has ? (acc[h][j] / sh[h]) : 0.f;
            if (j == 0)       v += res[(size_t)n * 188 + h * 47 + lane];
            else if (has2)    v += res[(size_t)n * 188 + h * 47 + 32 + lane];
            sm += v;
        }
        outv[j] = sm * 0.25f;
    }
    float lm = outv[0];
    if (has2) lm = fmaxf(lm, outv[1]);
    lm = fmaxf(lm, __shfl_xor_sync(0xffffffffu, lm, 16));
    lm = fmaxf(lm, __shfl_xor_sync(0xffffffffu, lm, 8));
    lm = fmaxf(lm, __shfl_xor_sync(0xffffffffu, lm, 4));
    lm = fmaxf(lm, __shfl_xor_sync(0xffffffffu, lm, 2));
    lm = fmaxf(lm, __shfl_xor_sync(0xffffffffu, lm, 1));
    float ls = __expf(outv[0] - lm) + (has2 ? __expf(outv[1] - lm) : 0.f);
    ls += __shfl_xor_sync(0xffffffffu, ls, 16);
    ls += __shfl_xor_sync(0xffffffffu, ls, 8);
    ls += __shfl_xor_sync(0xffffffffu, ls, 4);
    ls += __shfl_xor_sync(0xffffffffu, ls, 2);
    ls += __shfl_xor_sync(0xffffffffu, ls, 1);
    float lse = lm + logf(ls);
    out[(size_t)n * 47 + lane] = outv[0] - lse;
    if (has2) out[(size_t)n * 47 + 32 + lane] = outv[1] - lse;
}

// ---------------- BatchNorm (training batch stats), relu fused into apply ----------------
__global__ void bn_zero() {
    g_bnsum[threadIdx.x] = 0.f;
    g_bnsq[threadIdx.x]  = 0.f;
}

__global__ void bn_stats(const float* __restrict__ X, int nrows) {
    int col = threadIdx.x;  // 128 threads
    float s = 0.f, sq = 0.f;
    for (int r = blockIdx.x; r < nrows; r += gridDim.x) {
        float v = X[(size_t)r * 128 + col];
        s += v; sq += v * v;
    }
    atomicAdd(&g_bnsum[col], s);
    atomicAdd(&g_bnsq[col], sq);
}

__global__ void bn_apply(const float* __restrict__ X, float* __restrict__ Y,
                         const float* __restrict__ g, const float* __restrict__ b, int nrows) {
    int idx = blockIdx.x * blockDim.x + threadIdx.x;
    if (idx >= nrows * 128) return;
    int col = idx & 127;
    float inv_n = 1.0f / (float)nrows;
    float mu  = g_bnsum[col] * inv_n;
    float var = g_bnsq[col] * inv_n - mu * mu;
    float v = g[col] * (X[idx] - mu) * rsqrtf(var + BN_EPS) + b[col];
    Y[idx] = fmaxf(v, 0.f);
}

// ---------------- launch ----------------
extern "C" void kernel_launch(void* const* d_in, const int* in_sizes, int n_in,
                              void* d_out, int out_size) {
    const float* x     = (const float*)d_in[0];
    const int*   src   = (const int*)d_in[1];
    const int*   dst   = (const int*)d_in[2];
    const float* Wsrc0 = (const float*)d_in[3];  const float* bsrc0 = (const float*)d_in[4];
    const float* Wdst0 = (const float*)d_in[5];  const float* bdst0 = (const float*)d_in[6];
    const float* attn0 = (const float*)d_in[7];
    const float* Wres0 = (const float*)d_in[8];  const float* bres0 = (const float*)d_in[9];
    const float* Wsrc1 = (const float*)d_in[10]; const float* bsrc1 = (const float*)d_in[11];
    const float* Wdst1 = (const float*)d_in[12]; const float* bdst1 = (const float*)d_in[13];
    const float* attn1 = (const float*)d_in[14];
    const float* Wsrc2 = (const float*)d_in[15]; const float* bsrc2 = (const float*)d_in[16];
    const float* Wdst2 = (const float*)d_in[17]; const float* bdst2 = (const float*)d_in[18];
    const float* attn2 = (const float*)d_in[19];
    const float* Wres2 = (const float*)d_in[20]; const float* bres2 = (const float*)d_in[21];
    const float* g0    = (const float*)d_in[22]; const float* be0   = (const float*)d_in[23];
    const float* g1    = (const float*)d_in[24]; const float* be1   = (const float*)d_in[25];
    float* out = (float*)d_out;

    float *fs, *fd, *res, *hA, *hB;
    cudaGetSymbolAddress((void**)&fs,  g_fs);
    cudaGetSymbolAddress((void**)&fd,  g_fd);
    cudaGetSymbolAddress((void**)&res, g_res);
    cudaGetSymbolAddress((void**)&hA,  g_hA);
    cudaGetSymbolAddress((void**)&hB,  g_hB);

    const int N = NNODES, E = NEDGES;
    dim3 gG((N + BM - 1) / BM, 2);    // 128 output cols
    dim3 gG2((N + BM - 1) / BM, 3);   // 188 output cols
    int aggGrid = N / 8;
    int applyGrid = (N * 128 + 255) / 256;

    build_rowptr<<<(E + 255) / 256, 256>>>(dst, E, N);

    // ---- layer 0: x[N,100] -> 128, Linear residual ----
    gemm_tf32<<<gG, 256>>>(x, Wsrc0, bsrc0, fs, N, 100, 128);
    gemm_tf32<<<gG, 256>>>(x, Wdst0, bdst0, fd, N, 100, 128);
    gemm_tf32<<<gG, 256>>>(x, Wres0, bres0, res, N, 100, 128);
    gat_agg128<<<aggGrid, 256>>>(fs, fd, attn0, res, hA, src, N);
    bn_zero<<<1, 128>>>();
    bn_stats<<<512, 128>>>(hA, N);
    bn_apply<<<applyGrid, 256>>>(hA, hB, g0, be0, N);

    // ---- layer 1: 128 -> 128, Identity residual ----
    gemm_tf32<<<gG, 256>>>(hB, Wsrc1, bsrc1, fs, N, 128, 128);
    gemm_tf32<<<gG, 256>>>(hB, Wdst1, bdst1, fd, N, 128, 128);
    gat_agg128<<<aggGrid, 256>>>(fs, fd, attn1, hB, hA, src, N);
    bn_zero<<<1, 128>>>();
    bn_stats<<<512, 128>>>(hA, N);
    bn_apply<<<applyGrid, 256>>>(hA, hB, g1, be1, N);

    // ---- layer 2: 128 -> 188 (H=4, C=47), Linear residual; mean heads + log_softmax ----
    gemm_tf32<<<gG2, 256>>>(hB, Wsrc2, bsrc2, fs, N, 128, 188);
    gemm_tf32<<<gG2, 256>>>(hB, Wdst2, bdst2, fd, N, 128, 188);
    gemm_tf32<<<gG2, 256>>>(hB, Wres2, bres2, res, N, 128, 188);
    gat_agg_final<<<aggGrid, 256>>>(fs, fd, attn2, res, out, src, N);
}

// round 5
// speedup vs baseline: 1.7655x; 1.4647x over previous
#include <cuda_runtime.h>
#include <stdint.h>
#include <math.h>

#define NNODES 100000
#define NEDGES 1000000
#define FDIM   128
#define F2DIM  188
#define NCLS   47
#define NHEAD  4
#define BN_EPS 1e-5f

// ---------------- scratch (device globals; no allocation allowed) ----------------
__device__ float g_fs[(size_t)NNODES * F2DIM];
__device__ float g_fd[(size_t)NNODES * F2DIM];
__device__ float g_res[(size_t)NNODES * F2DIM];
__device__ float g_hA[(size_t)NNODES * FDIM];
__device__ float g_hB[(size_t)NNODES * FDIM];
__device__ int   g_rowptr[NNODES + 1];
__device__ float g_bnsum[FDIM];
__device__ float g_bnsq[FDIM];

// ---------------- CSR row_ptr from sorted dst ----------------
__global__ void build_rowptr(const int* __restrict__ dst, int E, int N) {
    int e = blockIdx.x * blockDim.x + threadIdx.x;
    if (e >= E) return;
    int d = dst[e];
    int dprev = (e == 0) ? -1 : dst[e - 1];
    for (int n = dprev + 1; n <= d; n++) g_rowptr[n] = e;
    if (e == E - 1) {
        for (int n = d + 1; n <= N; n++) g_rowptr[n] = E;
    }
}

// ---------------- cp.async helpers ----------------
__device__ __forceinline__ void cp_async16(uint32_t smem_addr, const void* gptr, int src_bytes) {
    asm volatile("cp.async.cg.shared.global [%0], [%1], 16, %2;\n"
                 :: "r"(smem_addr), "l"(gptr), "r"(src_bytes));
}
__device__ __forceinline__ void cp_commit() {
    asm volatile("cp.async.commit_group;\n");
}
template <int NN>
__device__ __forceinline__ void cp_wait() {
    asm volatile("cp.async.wait_group %0;\n" :: "n"(NN));
}

// ---------------- split-tf32 tensor-core GEMM, cp.async double-buffered ----------------
// C[nrows,ncols] = A[nrows,K] @ W[K,ncols] + bias, fp32-accurate via
// C = Ah*Bh + Ah*Bl + Al*Bh (hi/lo tf32 split, split at fragment-load time).
// Block tile 128x64, BK=16, 256 threads (8 warps, each warp 32x32), 2 smem stages.

#define BM 128
#define BNT 64
#define BKT 16
#define APAD 20    // A row stride (floats)
#define BSTR 72    // B row stride

__device__ __forceinline__ float tf32_rna(float x) {
    float r;
    asm("cvt.rna.tf32.f32 %0, %1;" : "=f"(r) : "f"(x));
    return r;
}

__device__ __forceinline__ void mma_tf32(float* d, const float* a, const float* b) {
    asm volatile(
        "mma.sync.aligned.m16n8k8.row.col.f32.tf32.tf32.f32 "
        "{%0,%1,%2,%3}, {%4,%5,%6,%7}, {%8,%9}, {%0,%1,%2,%3};"
        : "+f"(d[0]), "+f"(d[1]), "+f"(d[2]), "+f"(d[3])
        : "r"(__float_as_uint(a[0])), "r"(__float_as_uint(a[1])),
          "r"(__float_as_uint(a[2])), "r"(__float_as_uint(a[3])),
          "r"(__float_as_uint(b[0])), "r"(__float_as_uint(b[1])));
}

__global__ __launch_bounds__(256, 2)
void gemm_tf32(const float* __restrict__ A, const float* __restrict__ W,
               const float* __restrict__ bias, float* __restrict__ C,
               int nrows, int K, int ncols) {
    __shared__ float As[2][BM][APAD];
    __shared__ float Bs[2][BKT][BSTR];

    int tid = threadIdx.x;
    int warp = tid >> 5, lane = tid & 31;
    int wm = warp & 3;
    int wn = warp >> 2;
    int g = lane >> 2, t4 = lane & 3;
    int row0 = blockIdx.x * BM;
    int col0 = blockIdx.y * BNT;

    // loader mapping
    int a_row = tid >> 1;              // 0..127
    int a_kc  = (tid & 1) * 8;         // 0 or 8 (two 16B chunks: a_kc, a_kc+4)
    int b_kr  = tid >> 4;              // 0..15
    int b_nc  = (tid & 15) * 4;        // 0..60

    int arow_g = row0 + a_row;
    bool arow_ok = arow_g < nrows;
    const float* Arow = A + (size_t)(arow_ok ? arow_g : 0) * K;
    bool bcol_ok = (col0 + b_nc) < ncols;

    float acc[2][4][4];
#pragma unroll
    for (int mt = 0; mt < 2; mt++)
#pragma unroll
        for (int nt = 0; nt < 4; nt++)
#pragma unroll
            for (int r = 0; r < 4; r++) acc[mt][nt][r] = 0.f;

    int niter = (K + BKT - 1) / BKT;

    uint32_t sA0 = (uint32_t)__cvta_generic_to_shared(&As[0][a_row][a_kc]);
    uint32_t sA1 = (uint32_t)__cvta_generic_to_shared(&As[1][a_row][a_kc]);
    uint32_t sB0 = (uint32_t)__cvta_generic_to_shared(&Bs[0][b_kr][b_nc]);
    uint32_t sB1 = (uint32_t)__cvta_generic_to_shared(&Bs[1][b_kr][b_nc]);

    auto prefetch = [&](int stage, int k0) {
        uint32_t sA = stage ? sA1 : sA0;
        uint32_t sB = stage ? sB1 : sB0;
#pragma unroll
        for (int q = 0; q < 2; q++) {
            int kk = k0 + a_kc + 4 * q;
            int bytes = (arow_ok && (kk + 4 <= K)) ? 16 : 0;   // K is a multiple of 4
            cp_async16(sA + 16 * q, Arow + (bytes ? kk : 0), bytes);
        }
        {
            int kk = k0 + b_kr;
            int bytes = (bcol_ok && kk < K) ? 16 : 0;
            const float* src = W + (size_t)(bytes ? kk : 0) * ncols + col0 + (bytes ? b_nc : 0);
            cp_async16(sB, src, bytes);
        }
    };

    prefetch(0, 0);
    cp_commit();

    int buf = 0;
    for (int it = 0; it < niter; it++) {
        if (it + 1 < niter) prefetch(buf ^ 1, (it + 1) * BKT);
        cp_commit();
        cp_wait<1>();
        __syncthreads();

        // ---- compute stage buf: 2 k-steps of m16n8k8 ----
#pragma unroll
        for (int ks = 0; ks < 2; ks++) {
            int kb = ks * 8;
            float ah[2][4], al[2][4];
#pragma unroll
            for (int mt = 0; mt < 2; mt++) {
                int mr = wm * 32 + mt * 16 + g;
                float r0 = As[buf][mr][kb + t4];
                float r1 = As[buf][mr + 8][kb + t4];
                float r2 = As[buf][mr][kb + t4 + 4];
                float r3 = As[buf][mr + 8][kb + t4 + 4];
                ah[mt][0] = tf32_rna(r0); al[mt][0] = tf32_rna(r0 - ah[mt][0]);
                ah[mt][1] = tf32_rna(r1); al[mt][1] = tf32_rna(r1 - ah[mt][1]);
                ah[mt][2] = tf32_rna(r2); al[mt][2] = tf32_rna(r2 - ah[mt][2]);
                ah[mt][3] = tf32_rna(r3); al[mt][3] = tf32_rna(r3 - ah[mt][3]);
            }
            float bh[4][2], bl[4][2];
#pragma unroll
            for (int nt = 0; nt < 4; nt++) {
                int nc = wn * 32 + nt * 8 + g;
                float r0 = Bs[buf][kb + t4][nc];
                float r1 = Bs[buf][kb + t4 + 4][nc];
                bh[nt][0] = tf32_rna(r0); bl[nt][0] = tf32_rna(r0 - bh[nt][0]);
                bh[nt][1] = tf32_rna(r1); bl[nt][1] = tf32_rna(r1 - bh[nt][1]);
            }
#pragma unroll
            for (int mt = 0; mt < 2; mt++)
#pragma unroll
                for (int nt = 0; nt < 4; nt++) {
                    mma_tf32(acc[mt][nt], ah[mt], bh[nt]);
                    mma_tf32(acc[mt][nt], ah[mt], bl[nt]);
                    mma_tf32(acc[mt][nt], al[mt], bh[nt]);
                }
        }
        __syncthreads();
        buf ^= 1;
    }

    // ---- epilogue: bias add + store ----
#pragma unroll
    for (int mt = 0; mt < 2; mt++) {
#pragma unroll
        for (int nt = 0; nt < 4; nt++) {
            int row = row0 + wm * 32 + mt * 16 + g;
            int col = col0 + wn * 32 + nt * 8 + 2 * t4;
            if (col < ncols) {
                float b0 = bias[col], b1 = bias[col + 1];
                if (row < nrows) {
                    float2 v = make_float2(acc[mt][nt][0] + b0, acc[mt][nt][1] + b1);
                    *reinterpret_cast<float2*>(C + (size_t)row * ncols + col) = v;
                }
                if (row + 8 < nrows) {
                    float2 v = make_float2(acc[mt][nt][2] + b0, acc[mt][nt][3] + b1);
                    *reinterpret_cast<float2*>(C + (size_t)(row + 8) * ncols + col) = v;
                }
            }
        }
    }
}

// ---------------- GATv2 aggregation, F=128 (H=4, D=32) ----------------
// Warp per node. Lane = h*8+sub: lane owns float4 chunk sub of head h.
// Per edge: 1 LDG.128 + 3 shfl (all heads reduced simultaneously) + online softmax.
__global__ void gat_agg128(const float* __restrict__ fs, const float* __restrict__ fd,
                           const float* __restrict__ attn, const float* __restrict__ res,
                           float* __restrict__ out, const int* __restrict__ srcidx, int N) {
    int warp = (blockIdx.x * blockDim.x + threadIdx.x) >> 5;
    int lane = threadIdx.x & 31;
    if (warp >= N) return;
    int n = warp;
    const float4* fs4   = (const float4*)fs;
    const float4* fd4   = (const float4*)fd;
    const float4* attn4 = (const float4*)attn;
    const float4* res4  = (const float4*)res;
    float4* out4 = (float4*)out;

    float4 fdv = fd4[(size_t)n * 32 + lane];
    float4 av  = attn4[lane];
    float4 acc = make_float4(0.f, 0.f, 0.f, 0.f);
    float m = -1e30f, s = 0.f;

    int e0 = g_rowptr[n], e1 = g_rowptr[n + 1];
    float4 fsv = make_float4(0.f, 0.f, 0.f, 0.f);
    if (e0 < e1) {
        int si = __ldg(&srcidx[e0]);
        fsv = __ldg(&fs4[(size_t)si * 32 + lane]);
    }
    for (int e = e0; e < e1; e++) {
        float4 cur = fsv;
        if (e + 1 < e1) {
            int sn = __ldg(&srcidx[e + 1]);
            fsv = __ldg(&fs4[(size_t)sn * 32 + lane]);
        }
        float vx = cur.x + fdv.x; vx = (vx > 0.f) ? vx : 0.2f * vx;
        float vy = cur.y + fdv.y; vy = (vy > 0.f) ? vy : 0.2f * vy;
        float vz = cur.z + fdv.z; vz = (vz > 0.f) ? vz : 0.2f * vz;
        float vw = cur.w + fdv.w; vw = (vw > 0.f) ? vw : 0.2f * vw;
        float t = vx * av.x + vy * av.y + vz * av.z + vw * av.w;
        t += __shfl_xor_sync(0xffffffffu, t, 4);
        t += __shfl_xor_sync(0xffffffffu, t, 2);
        t += __shfl_xor_sync(0xffffffffu, t, 1);
        if (t > m) {
            float c = __expf(m - t);
            acc.x *= c; acc.y *= c; acc.z *= c; acc.w *= c;
            s *= c; m = t;
        }
        float p = __expf(t - m);
        s += p;
        acc.x = fmaf(p, cur.x, acc.x);
        acc.y = fmaf(p, cur.y, acc.y);
        acc.z = fmaf(p, cur.z, acc.z);
        acc.w = fmaf(p, cur.w, acc.w);
    }
    float inv = (e1 > e0) ? (1.f / s) : 0.f;
    float4 r = res4[(size_t)n * 32 + lane];
    float4 o;
    o.x = fmaxf(fmaf(acc.x, inv, r.x), 0.f);
    o.y = fmaxf(fmaf(acc.y, inv, r.y), 0.f);
    o.z = fmaxf(fmaf(acc.z, inv, r.z), 0.f);
    o.w = fmaxf(fmaf(acc.w, inv, r.w), 0.f);
    out4[(size_t)n * 32 + lane] = o;
}

// ---------------- Layer-2 aggregation (C=47) + head-mean + log_softmax ----------------
// Lane = h*8+sub; lane owns classes [sub*6, sub*6+6) of head h (sub=7: 5 classes).
__global__ void gat_agg_final(const float* __restrict__ fs, const float* __restrict__ fd,
                              const float* __restrict__ attn, const float* __restrict__ res,
                              float* __restrict__ out, const int* __restrict__ srcidx, int N) {
    int warp = (blockIdx.x * blockDim.x + threadIdx.x) >> 5;
    int lane = threadIdx.x & 31;
    if (warp >= N) return;
    int n = warp;
    int h = lane >> 3, sub = lane & 7;
    int c0 = sub * 6;
    int cnt = (47 - c0 < 6) ? (47 - c0) : 6;   // 6 or 5
    int base = h * 47 + c0;

    float fdv[6], av[6], acc[6];
#pragma unroll
    for (int j = 0; j < 6; j++) {
        bool valid = j < cnt;
        fdv[j] = valid ? fd[(size_t)n * 188 + base + j] : 0.f;
        av[j]  = valid ? attn[base + j] : 0.f;
        acc[j] = 0.f;
    }
    float m = -1e30f, s = 0.f;

    int e0 = g_rowptr[n], e1 = g_rowptr[n + 1];
    float fsv[6];
#pragma unroll
    for (int j = 0; j < 6; j++) fsv[j] = 0.f;
    if (e0 < e1) {
        int si = __ldg(&srcidx[e0]);
        const float* p = fs + (size_t)si * 188 + base;
#pragma unroll
        for (int j = 0; j < 6; j++) if (j < cnt) fsv[j] = __ldg(&p[j]);
    }
    for (int e = e0; e < e1; e++) {
        float cur[6];
#pragma unroll
        for (int j = 0; j < 6; j++) cur[j] = fsv[j];
        if (e + 1 < e1) {
            int sn = __ldg(&srcidx[e + 1]);
            const float* p = fs + (size_t)sn * 188 + base;
#pragma unroll
            for (int j = 0; j < 6; j++) if (j < cnt) fsv[j] = __ldg(&p[j]);
        }
        float t = 0.f;
#pragma unroll
        for (int j = 0; j < 6; j++) {
            float v = cur[j] + fdv[j];
            v = (v > 0.f) ? v : 0.2f * v;
            t = fmaf(v, av[j], t);
        }
        t += __shfl_xor_sync(0xffffffffu, t, 4);
        t += __shfl_xor_sync(0xffffffffu, t, 2);
        t += __shfl_xor_sync(0xffffffffu, t, 1);
        if (t > m) {
            float c = __expf(m - t);
#pragma unroll
            for (int j = 0; j < 6; j++) acc[j] *= c;
            s *= c; m = t;
        }
        float p = __expf(t - m);
        s += p;
#pragma unroll
        for (int j = 0; j < 6; j++) acc[j] = fmaf(p, cur[j], acc[j]);
    }
    float inv = (e1 > e0) ? (1.f / s) : 0.f;
    float v[6];
#pragma unroll
    for (int j = 0; j < 6; j++) {
        float rr = (j < cnt) ? res[(size_t)n * 188 + base + j] : 0.f;
        v[j] = fmaf(acc[j], inv, rr);
    }
    // head mean: sum over h (xor bits 3,4), then *0.25
#pragma unroll
    for (int j = 0; j < 6; j++) {
        v[j] += __shfl_xor_sync(0xffffffffu, v[j], 8);
        v[j] += __shfl_xor_sync(0xffffffffu, v[j], 16);
        v[j] *= 0.25f;
    }
    // log_softmax over 47 classes spread over sub groups (identical across h)
    float lm = -1e30f;
#pragma unroll
    for (int j = 0; j < 6; j++) if (j < cnt) lm = fmaxf(lm, v[j]);
    lm = fmaxf(lm, __shfl_xor_sync(0xffffffffu, lm, 4));
    lm = fmaxf(lm, __shfl_xor_sync(0xffffffffu, lm, 2));
    lm = fmaxf(lm, __shfl_xor_sync(0xffffffffu, lm, 1));
    float ls = 0.f;
#pragma unroll
    for (int j = 0; j < 6; j++) if (j < cnt) ls += __expf(v[j] - lm);
    ls += __shfl_xor_sync(0xffffffffu, ls, 4);
    ls += __shfl_xor_sync(0xffffffffu, ls, 2);
    ls += __shfl_xor_sync(0xffffffffu, ls, 1);
    float lse = lm + logf(ls);
    if (h == 0) {
#pragma unroll
        for (int j = 0; j < 6; j++)
            if (j < cnt) out[(size_t)n * 47 + c0 + j] = v[j] - lse;
    }
}

// ---------------- BatchNorm (training batch stats), relu fused into apply ----------------
__global__ void bn_zero() {
    g_bnsum[threadIdx.x] = 0.f;
    g_bnsq[threadIdx.x]  = 0.f;
}

__global__ void bn_stats(const float* __restrict__ X, int nrows) {
    int col = threadIdx.x;  // 128 threads
    float s = 0.f, sq = 0.f;
    for (int r = blockIdx.x; r < nrows; r += gridDim.x) {
        float v = X[(size_t)r * 128 + col];
        s += v; sq += v * v;
    }
    atomicAdd(&g_bnsum[col], s);
    atomicAdd(&g_bnsq[col], sq);
}

__global__ void bn_apply(const float* __restrict__ X, float* __restrict__ Y,
                         const float* __restrict__ g, const float* __restrict__ b, int nrows) {
    int idx = blockIdx.x * blockDim.x + threadIdx.x;
    if (idx >= nrows * 128) return;
    int col = idx & 127;
    float inv_n = 1.0f / (float)nrows;
    float mu  = g_bnsum[col] * inv_n;
    float var = g_bnsq[col] * inv_n - mu * mu;
    float v = g[col] * (X[idx] - mu) * rsqrtf(var + BN_EPS) + b[col];
    Y[idx] = fmaxf(v, 0.f);
}

// ---------------- launch ----------------
extern "C" void kernel_launch(void* const* d_in, const int* in_sizes, int n_in,
                              void* d_out, int out_size) {
    const float* x     = (const float*)d_in[0];
    const int*   src   = (const int*)d_in[1];
    const int*   dst   = (const int*)d_in[2];
    const float* Wsrc0 = (const float*)d_in[3];  const float* bsrc0 = (const float*)d_in[4];
    const float* Wdst0 = (const float*)d_in[5];  const float* bdst0 = (const float*)d_in[6];
    const float* attn0 = (const float*)d_in[7];
    const float* Wres0 = (const float*)d_in[8];  const float* bres0 = (const float*)d_in[9];
    const float* Wsrc1 = (const float*)d_in[10]; const float* bsrc1 = (const float*)d_in[11];
    const float* Wdst1 = (const float*)d_in[12]; const float* bdst1 = (const float*)d_in[13];
    const float* attn1 = (const float*)d_in[14];
    const float* Wsrc2 = (const float*)d_in[15]; const float* bsrc2 = (const float*)d_in[16];
    const float* Wdst2 = (const float*)d_in[17]; const float* bdst2 = (const float*)d_in[18];
    const float* attn2 = (const float*)d_in[19];
    const float* Wres2 = (const float*)d_in[20]; const float* bres2 = (const float*)d_in[21];
    const float* g0    = (const float*)d_in[22]; const float* be0   = (const float*)d_in[23];
    const float* g1    = (const float*)d_in[24]; const float* be1   = (const float*)d_in[25];
    float* out = (float*)d_out;

    float *fs, *fd, *res, *hA, *hB;
    cudaGetSymbolAddress((void**)&fs,  g_fs);
    cudaGetSymbolAddress((void**)&fd,  g_fd);
    cudaGetSymbolAddress((void**)&res, g_res);
    cudaGetSymbolAddress((void**)&hA,  g_hA);
    cudaGetSymbolAddress((void**)&hB,  g_hB);

    const int N = NNODES, E = NEDGES;
    dim3 gG((N + BM - 1) / BM, 2);    // 128 output cols
    dim3 gG2((N + BM - 1) / BM, 3);   // 188 output cols
    int aggGrid = N / 8;
    int applyGrid = (N * 128 + 255) / 256;

    build_rowptr<<<(E + 255) / 256, 256>>>(dst, E, N);

    // ---- layer 0: x[N,100] -> 128, Linear residual ----
    gemm_tf32<<<gG, 256>>>(x, Wsrc0, bsrc0, fs, N, 100, 128);
    gemm_tf32<<<gG, 256>>>(x, Wdst0, bdst0, fd, N, 100, 128);
    gemm_tf32<<<gG, 256>>>(x, Wres0, bres0, res, N, 100, 128);
    gat_agg128<<<aggGrid, 256>>>(fs, fd, attn0, res, hA, src, N);
    bn_zero<<<1, 128>>>();
    bn_stats<<<512, 128>>>(hA, N);
    bn_apply<<<applyGrid, 256>>>(hA, hB, g0, be0, N);

    // ---- layer 1: 128 -> 128, Identity residual ----
    gemm_tf32<<<gG, 256>>>(hB, Wsrc1, bsrc1, fs, N, 128, 128);
    gemm_tf32<<<gG, 256>>>(hB, Wdst1, bdst1, fd, N, 128, 128);
    gat_agg128<<<aggGrid, 256>>>(fs, fd, attn1, hB, hA, src, N);
    bn_zero<<<1, 128>>>();
    bn_stats<<<512, 128>>>(hA, N);
    bn_apply<<<applyGrid, 256>>>(hA, hB, g1, be1, N);

    // ---- layer 2: 128 -> 188 (H=4, C=47), Linear residual; mean heads + log_softmax ----
    gemm_tf32<<<gG2, 256>>>(hB, Wsrc2, bsrc2, fs, N, 128, 188);
    gemm_tf32<<<gG2, 256>>>(hB, Wdst2, bdst2, fd, N, 128, 188);
    gemm_tf32<<<gG2, 256>>>(hB, Wres2, bres2, res, N, 128, 188);
    gat_agg_final<<<aggGrid, 256>>>(fs, fd, attn2, res, out, src, N);
}